// round 2
// baseline (speedup 1.0000x reference)
#include <cuda_runtime.h>
#include <math.h>

#define NB 2
#define NF 4096
#define NQ 16384
#define NPTS (NB*NQ)                 // 32768
#define BLOCK 128
#define SPLITS 2
#define TRIS_PER_SPLIT (NF/SPLITS)   // 2048
#define TILE 512

// Scratch (static __device__ arrays: allowed; no allocs anywhere)
__device__ float4 g_tc[NB*NF*4];              // 16 floats per triangle
__device__ uint2  g_cand[NPTS*SPLITS];        // per (point,split): top-2 triangle indices

__device__ __forceinline__ float guard_inv(float x) {
    return (fabsf(x) > 1e-12f) ? (1.0f / x) : 1.0f;
}
__device__ __forceinline__ float clamp01(float x) {
    return fminf(fmaxf(x, 0.0f), 1.0f);
}
__device__ __forceinline__ double dclamp01(double x) {
    return fmin(fmax(x, 0.0), 1.0);
}
__device__ __forceinline__ double dsafe_div(double num, double den) {
    double d = (fabs(den) > 1e-12) ? den : 1.0;
    return num / d;
}

// ---------------------------------------------------------------------------
// Kernel 0: per-triangle constants: a, ab, ac, aa, bb, g, + guarded reciprocals
// of the 4 per-triangle denominators.
// ---------------------------------------------------------------------------
__global__ void k_pre(const float* __restrict__ tris) {
    int i = blockIdx.x * blockDim.x + threadIdx.x;
    if (i >= NB * NF) return;
    const float* t = tris + (size_t)i * 9;
    float ax = t[0], ay = t[1], az = t[2];
    float bx = t[3], by = t[4], bz = t[5];
    float cx = t[6], cy = t[7], cz = t[8];
    float abx = bx - ax, aby = by - ay, abz = bz - az;
    float acx = cx - ax, acy = cy - ay, acz = cz - az;
    float aa = abx*abx + aby*aby + abz*abz;      // == d1 - d3
    float bb = acx*acx + acy*acy + acz*acz;      // == d2 - d6
    float gg = abx*acx + aby*acy + abz*acz;      // ab . ac
    float cb2 = aa + bb - 2.0f*gg;               // == (d4-d3)+(d5-d6)
    float den = aa*bb - gg*gg;                   // == va+vb+vc
    float4* o = g_tc + (size_t)i * 4;
    o[0] = make_float4(ax, ay, az, abx);
    o[1] = make_float4(aby, abz, acx, acy);
    o[2] = make_float4(acz, aa, bb, gg);
    o[3] = make_float4(guard_inv(aa), guard_inv(bb), guard_inv(cb2), guard_inv(den));
}

// ---------------------------------------------------------------------------
// Kernel 1: brute-force scan. 1 point/thread, triangles split across blockIdx.y,
// constants staged through SMEM tiles. Division-free. Tracks TOP-2 candidates
// per (point, split); phase 2 arbitrates near-ties in double precision.
// ---------------------------------------------------------------------------
__global__ void __launch_bounds__(BLOCK) k_main(const float* __restrict__ points) {
    __shared__ float4 sh[TILE * 4];
    int b = blockIdx.z;
    int q = blockIdx.x * BLOCK + threadIdx.x;
    const float* pp = points + (size_t)(b * NQ + q) * 3;
    float px = pp[0], py = pp[1], pz = pp[2];
    int triBase = blockIdx.y * TRIS_PER_SPLIT;

    float best  = 3.402823e38f;  int bidx  = triBase;
    float best2 = 3.402823e38f;  int bidx2 = triBase;

    for (int tile = 0; tile < TRIS_PER_SPLIT; tile += TILE) {
        __syncthreads();
        const float4* src = g_tc + (size_t)(b * NF + triBase + tile) * 4;
        for (int i = threadIdx.x; i < TILE * 4; i += BLOCK) sh[i] = src[i];
        __syncthreads();

        #pragma unroll 2
        for (int j = 0; j < TILE; j++) {
            float4 t0 = sh[j*4+0], t1 = sh[j*4+1], t2 = sh[j*4+2], t3 = sh[j*4+3];
            float apx = px - t0.x, apy = py - t0.y, apz = pz - t0.z;
            float abx = t0.w, aby = t1.x, abz = t1.y;
            float acx = t1.z, acy = t1.w, acz = t2.x;
            float aa = t2.y, bb = t2.z, gg = t2.w;

            float d1 = fmaf(abx, apx, fmaf(aby, apy, abz * apz));
            float d2 = fmaf(acx, apx, fmaf(acy, apy, acz * apz));
            float d3 = d1 - aa;
            float d4 = d2 - gg;
            float d5 = d1 - gg;
            float d6 = d2 - bb;

            float vc = fmaf(d1, d4, -d3 * d2);
            float vb = fmaf(d5, d2, -d1 * d6);
            float va = fmaf(d3, d6, -d5 * d4);
            float e1 = d4 - d3;   // edge-BC numerator
            float e2 = d5 - d6;

            // interior (lowest precedence)
            float v = vb * t3.w;
            float w = vc * t3.w;
            // edge BC
            bool mbc = (va <= 0.0f) && (e1 >= 0.0f) && (e2 >= 0.0f);
            float wbc = clamp01(e1 * t3.z);
            v = mbc ? (1.0f - wbc) : v;  w = mbc ? wbc : w;
            // edge AC
            bool mac = (vb <= 0.0f) && (d2 >= 0.0f) && (d6 <= 0.0f);
            float wac = clamp01(d2 * t3.y);
            v = mac ? 0.0f : v;  w = mac ? wac : w;
            // edge AB
            bool mab = (vc <= 0.0f) && (d1 >= 0.0f) && (d3 <= 0.0f);
            float vab = clamp01(d1 * t3.x);
            v = mab ? vab : v;   w = mab ? 0.0f : w;
            // vertex C
            bool mc = (d6 >= 0.0f) && (e2 <= 0.0f);
            v = mc ? 0.0f : v;   w = mc ? 1.0f : w;
            // vertex B
            bool mb = (d3 >= 0.0f) && (e1 <= 0.0f);
            v = mb ? 1.0f : v;   w = mb ? 0.0f : w;
            // vertex A (highest precedence)
            bool ma = (d1 <= 0.0f) && (d2 <= 0.0f);
            v = ma ? 0.0f : v;   w = ma ? 0.0f : w;

            float dx = fmaf(-v, abx, fmaf(-w, acx, apx));
            float dy = fmaf(-v, aby, fmaf(-w, acy, apy));
            float dz = fmaf(-v, abz, fmaf(-w, acz, apz));
            float dist = fmaf(dx, dx, fmaf(dy, dy, dz * dz));

            int t = triBase + tile + j;
            bool lt1 = dist < best;
            bool lt2 = dist < best2;
            best2 = lt1 ? best : (lt2 ? dist : best2);
            bidx2 = lt1 ? bidx : (lt2 ? t    : bidx2);
            best  = lt1 ? dist : best;
            bidx  = lt1 ? t    : bidx;
        }
    }

    g_cand[(size_t)(b * NQ + q) * SPLITS + blockIdx.y] =
        make_uint2((unsigned)bidx, (unsigned)bidx2);
}

// ---------------------------------------------------------------------------
// Reference formula in DOUBLE precision (true-math ordering for arbitration).
// Returns squared distance; writes closest point.
// ---------------------------------------------------------------------------
__device__ void ref_eval_d(const float* __restrict__ tp,
                           double px, double py, double pz,
                           double& d2out, double& rxo, double& ryo, double& rzo) {
    double ax = tp[0], ay = tp[1], az = tp[2];
    double bx = tp[3], by = tp[4], bz = tp[5];
    double cx = tp[6], cy = tp[7], cz = tp[8];

    double abx = bx - ax, aby = by - ay, abz = bz - az;
    double acx = cx - ax, acy = cy - ay, acz = cz - az;
    double apx = px - ax, apy = py - ay, apz = pz - az;
    double d1 = abx*apx + aby*apy + abz*apz;
    double d2 = acx*apx + acy*apy + acz*apz;
    double bpx = px - bx, bpy = py - by, bpz = pz - bz;
    double d3 = abx*bpx + aby*bpy + abz*bpz;
    double d4 = acx*bpx + acy*bpy + acz*bpz;
    double cpx = px - cx, cpy = py - cy, cpz = pz - cz;
    double d5 = abx*cpx + aby*cpy + abz*cpz;
    double d6 = acx*cpx + acy*cpy + acz*cpz;

    double vc = d1*d4 - d3*d2;
    double vb = d5*d2 - d1*d6;
    double va = d3*d6 - d5*d4;
    double v_ab = dclamp01(dsafe_div(d1, d1 - d3));
    double w_ac = dclamp01(dsafe_div(d2, d2 - d6));
    double w_bc = dclamp01(dsafe_div(d4 - d3, (d4 - d3) + (d5 - d6)));
    double denom = va + vb + vc;
    double v = dsafe_div(vb, denom);
    double w = dsafe_div(vc, denom);

    double rx = ax + abx*v + acx*w;
    double ry = ay + aby*v + acy*w;
    double rz = az + abz*v + acz*w;

    bool m_bc = (va <= 0.0) && ((d4 - d3) >= 0.0) && ((d5 - d6) >= 0.0);
    if (m_bc) { rx = bx + w_bc*(cx - bx); ry = by + w_bc*(cy - by); rz = bz + w_bc*(cz - bz); }
    bool m_ac = (vb <= 0.0) && (d2 >= 0.0) && (d6 <= 0.0);
    if (m_ac) { rx = ax + w_ac*acx; ry = ay + w_ac*acy; rz = az + w_ac*acz; }
    bool m_ab = (vc <= 0.0) && (d1 >= 0.0) && (d3 <= 0.0);
    if (m_ab) { rx = ax + v_ab*abx; ry = ay + v_ab*aby; rz = az + v_ab*abz; }
    bool m_c = (d6 >= 0.0) && (d5 <= d6);
    if (m_c) { rx = cx; ry = cy; rz = cz; }
    bool m_b = (d3 >= 0.0) && (d4 <= d3);
    if (m_b) { rx = bx; ry = by; rz = bz; }
    bool m_a = (d1 <= 0.0) && (d2 <= 0.0);
    if (m_a) { rx = ax; ry = ay; rz = az; }

    double dxx = px - rx, dyy = py - ry, dzz = pz - rz;
    d2out = dxx*dxx + dyy*dyy + dzz*dzz;
    rxo = rx; ryo = ry; rzo = rz;
}

// ---------------------------------------------------------------------------
// Kernel 2: arbitrate the <=4 candidates per point in double precision and
// write outputs: dist[32768] | closest[32768*3] | faces[32768] (as float).
// ---------------------------------------------------------------------------
__global__ void k_fin(const float* __restrict__ tris,
                      const float* __restrict__ points,
                      float* __restrict__ out) {
    int i = blockIdx.x * blockDim.x + threadIdx.x;
    if (i >= NPTS) return;
    int b = i / NQ;

    uint2 c0 = g_cand[(size_t)i * SPLITS + 0];
    uint2 c1 = g_cand[(size_t)i * SPLITS + 1];
    int cand[4] = {(int)c0.x, (int)c0.y, (int)c1.x, (int)c1.y};

    const float* pp = points + (size_t)i * 3;
    double px = pp[0], py = pp[1], pz = pp[2];

    double bestD = 1e300, brx = 0, bry = 0, brz = 0;
    int bestI = 0x7FFFFFFF;

    #pragma unroll
    for (int k = 0; k < 4; k++) {
        int idx = cand[k];
        const float* tp = tris + (size_t)(b * NF + idx) * 9;
        double d2, rx, ry, rz;
        ref_eval_d(tp, px, py, pz, d2, rx, ry, rz);
        bool take = (d2 < bestD) || (d2 == bestD && idx < bestI);
        if (take) { bestD = d2; bestI = idx; brx = rx; bry = ry; brz = rz; }
    }

    out[i] = (float)bestD;                               // distances [2,16384]
    out[NPTS + (size_t)i*3 + 0] = (float)brx;            // closest_points [2,16384,3]
    out[NPTS + (size_t)i*3 + 1] = (float)bry;
    out[NPTS + (size_t)i*3 + 2] = (float)brz;
    out[(size_t)NPTS*4 + i] = (float)bestI;              // closest_faces [2,16384]
}

extern "C" void kernel_launch(void* const* d_in, const int* in_sizes, int n_in,
                              void* d_out, int out_size) {
    const float* tris = (const float*)d_in[0];   // [2,4096,3,3]
    const float* pts  = (const float*)d_in[1];   // [2,16384,3]
    float* out = (float*)d_out;

    k_pre<<<(NB*NF + 255) / 256, 256>>>(tris);
    dim3 grid(NQ / BLOCK, SPLITS, NB);
    k_main<<<grid, BLOCK>>>(pts);
    k_fin<<<(NPTS + 255) / 256, 256>>>(tris, pts, out);
}

// round 4
// speedup vs baseline: 1.1548x; 1.1548x over previous
#include <cuda_runtime.h>
#include <math.h>

#define NB 2
#define NF 4096
#define NQ 16384
#define NPTS (NB*NQ)                 // 32768
#define BLOCK 128
#define SPLITS 4
#define TRIS_PER_SPLIT (NF/SPLITS)   // 1024
#define TILE 256

// Scratch (static __device__ arrays: allowed; no allocs anywhere)
__device__ float4 g_tc[NB*NF*4];              // 16 floats per triangle
__device__ uint2  g_cand[NPTS*SPLITS];        // per (point,split): top-2 triangle indices

__device__ __forceinline__ float guard_inv(float x) {
    return (fabsf(x) > 1e-12f) ? (1.0f / x) : 1.0f;
}
__device__ __forceinline__ float clamp01(float x) {
    return fminf(fmaxf(x, 0.0f), 1.0f);
}
__device__ __forceinline__ double dclamp01(double x) {
    return fmin(fmax(x, 0.0), 1.0);
}
__device__ __forceinline__ double dsafe_div(double num, double den) {
    double d = (fabs(den) > 1e-12) ? den : 1.0;
    return num / d;
}

// ---------------------------------------------------------------------------
// Kernel 0: per-triangle constants (R2 layout, proven):
//  o0 = (ax, ay, az, abx)   o1 = (aby, abz, acx, acy)
//  o2 = (acz, aa, bb, gg)   o3 = (inv_aa, inv_bb, inv_cb2, inv_den)
// ---------------------------------------------------------------------------
__global__ void k_pre(const float* __restrict__ tris) {
    int i = blockIdx.x * blockDim.x + threadIdx.x;
    if (i >= NB * NF) return;
    const float* t = tris + (size_t)i * 9;
    float ax = t[0], ay = t[1], az = t[2];
    float bx = t[3], by = t[4], bz = t[5];
    float cx = t[6], cy = t[7], cz = t[8];
    float abx = bx - ax, aby = by - ay, abz = bz - az;
    float acx = cx - ax, acy = cy - ay, acz = cz - az;
    float aa = abx*abx + aby*aby + abz*abz;      // == d1 - d3
    float bb = acx*acx + acy*acy + acz*acz;      // == d2 - d6
    float gg = abx*acx + aby*acy + abz*acz;      // ab . ac
    float cb2 = aa + bb - 2.0f*gg;               // == (d4-d3)+(d5-d6)
    float den = aa*bb - gg*gg;                   // == va+vb+vc
    float4* o = g_tc + (size_t)i * 4;
    o[0] = make_float4(ax, ay, az, abx);
    o[1] = make_float4(aby, abz, acx, acy);
    o[2] = make_float4(acz, aa, bb, gg);
    o[3] = make_float4(guard_inv(aa), guard_inv(bb), guard_inv(cb2), guard_inv(den));
}

// ---------------------------------------------------------------------------
// Kernel 1: brute-force scan (R2 math: vector-form distance + region selects).
// 1 point/thread, triangles split over blockIdx.y (4 splits for occupancy),
// constants staged through SMEM tiles. Division-free. Top-2 per split.
// ---------------------------------------------------------------------------
__global__ void __launch_bounds__(BLOCK) k_main(const float* __restrict__ points) {
    __shared__ float4 sh[TILE * 4];
    int b = blockIdx.z;
    int q = blockIdx.x * BLOCK + threadIdx.x;
    const float* pp = points + (size_t)(b * NQ + q) * 3;
    float px = pp[0], py = pp[1], pz = pp[2];
    int triBase = blockIdx.y * TRIS_PER_SPLIT;

    float best  = 3.402823e38f;  int bidx  = triBase;
    float best2 = 3.402823e38f;  int bidx2 = triBase;

    for (int tile = 0; tile < TRIS_PER_SPLIT; tile += TILE) {
        __syncthreads();
        const float4* src = g_tc + (size_t)(b * NF + triBase + tile) * 4;
        for (int i = threadIdx.x; i < TILE * 4; i += BLOCK) sh[i] = src[i];
        __syncthreads();

        #pragma unroll 4
        for (int j = 0; j < TILE; j++) {
            float4 t0 = sh[j*4+0], t1 = sh[j*4+1], t2 = sh[j*4+2], t3 = sh[j*4+3];
            float apx = px - t0.x, apy = py - t0.y, apz = pz - t0.z;
            float abx = t0.w, aby = t1.x, abz = t1.y;
            float acx = t1.z, acy = t1.w, acz = t2.x;
            float aa = t2.y, bb = t2.z, gg = t2.w;

            float d1 = fmaf(abx, apx, fmaf(aby, apy, abz * apz));
            float d2 = fmaf(acx, apx, fmaf(acy, apy, acz * apz));
            float d3 = d1 - aa;
            float d4 = d2 - gg;
            float d5 = d1 - gg;
            float d6 = d2 - bb;

            float vc = fmaf(d1, d4, -d3 * d2);
            float vb = fmaf(d5, d2, -d1 * d6);
            float va = fmaf(d3, d6, -d5 * d4);
            float e1 = d4 - d3;   // edge-BC numerator
            float e2 = d5 - d6;

            // interior (lowest precedence)
            float v = vb * t3.w;
            float w = vc * t3.w;
            // edge BC
            bool mbc = (va <= 0.0f) && (e1 >= 0.0f) && (e2 >= 0.0f);
            float wbc = clamp01(e1 * t3.z);
            v = mbc ? (1.0f - wbc) : v;  w = mbc ? wbc : w;
            // edge AC
            bool mac = (vb <= 0.0f) && (d2 >= 0.0f) && (d6 <= 0.0f);
            float wac = clamp01(d2 * t3.y);
            v = mac ? 0.0f : v;  w = mac ? wac : w;
            // edge AB
            bool mab = (vc <= 0.0f) && (d1 >= 0.0f) && (d3 <= 0.0f);
            float vab = clamp01(d1 * t3.x);
            v = mab ? vab : v;   w = mab ? 0.0f : w;
            // vertex C
            bool mc = (d6 >= 0.0f) && (e2 <= 0.0f);
            v = mc ? 0.0f : v;   w = mc ? 1.0f : w;
            // vertex B
            bool mb = (d3 >= 0.0f) && (e1 <= 0.0f);
            v = mb ? 1.0f : v;   w = mb ? 0.0f : w;
            // vertex A (highest precedence)
            bool ma = (d1 <= 0.0f) && (d2 <= 0.0f);
            v = ma ? 0.0f : v;   w = ma ? 0.0f : w;

            // vector-form distance (small residual components -> tight ordering)
            float dx = fmaf(-v, abx, fmaf(-w, acx, apx));
            float dy = fmaf(-v, aby, fmaf(-w, acy, apy));
            float dz = fmaf(-v, abz, fmaf(-w, acz, apz));
            float dist = fmaf(dx, dx, fmaf(dy, dy, dz * dz));

            int t = triBase + tile + j;
            bool lt1 = dist < best;
            bool lt2 = dist < best2;
            best2 = lt1 ? best : (lt2 ? dist : best2);
            bidx2 = lt1 ? bidx : (lt2 ? t    : bidx2);
            best  = lt1 ? dist : best;
            bidx  = lt1 ? t    : bidx;
        }
    }

    g_cand[(size_t)(b * NQ + q) * SPLITS + blockIdx.y] =
        make_uint2((unsigned)bidx, (unsigned)bidx2);
}

// ---------------------------------------------------------------------------
// Reference formula in DOUBLE precision (true-math ordering for arbitration).
// ---------------------------------------------------------------------------
__device__ void ref_eval_d(const float* __restrict__ tp,
                           double px, double py, double pz,
                           double& d2out, double& rxo, double& ryo, double& rzo) {
    double ax = tp[0], ay = tp[1], az = tp[2];
    double bx = tp[3], by = tp[4], bz = tp[5];
    double cx = tp[6], cy = tp[7], cz = tp[8];

    double abx = bx - ax, aby = by - ay, abz = bz - az;
    double acx = cx - ax, acy = cy - ay, acz = cz - az;
    double apx = px - ax, apy = py - ay, apz = pz - az;
    double d1 = abx*apx + aby*apy + abz*apz;
    double d2 = acx*apx + acy*apy + acz*apz;
    double bpx = px - bx, bpy = py - by, bpz = pz - bz;
    double d3 = abx*bpx + aby*bpy + abz*bpz;
    double d4 = acx*bpx + acy*bpy + acz*bpz;
    double cpx = px - cx, cpy = py - cy, cpz = pz - cz;
    double d5 = abx*cpx + aby*cpy + abz*cpz;
    double d6 = acx*cpx + acy*cpy + acz*cpz;

    double vc = d1*d4 - d3*d2;
    double vb = d5*d2 - d1*d6;
    double va = d3*d6 - d5*d4;
    double v_ab = dclamp01(dsafe_div(d1, d1 - d3));
    double w_ac = dclamp01(dsafe_div(d2, d2 - d6));
    double w_bc = dclamp01(dsafe_div(d4 - d3, (d4 - d3) + (d5 - d6)));
    double denom = va + vb + vc;
    double v = dsafe_div(vb, denom);
    double w = dsafe_div(vc, denom);

    double rx = ax + abx*v + acx*w;
    double ry = ay + aby*v + acy*w;
    double rz = az + abz*v + acz*w;

    bool m_bc = (va <= 0.0) && ((d4 - d3) >= 0.0) && ((d5 - d6) >= 0.0);
    if (m_bc) { rx = bx + w_bc*(cx - bx); ry = by + w_bc*(cy - by); rz = bz + w_bc*(cz - bz); }
    bool m_ac = (vb <= 0.0) && (d2 >= 0.0) && (d6 <= 0.0);
    if (m_ac) { rx = ax + w_ac*acx; ry = ay + w_ac*acy; rz = az + w_ac*acz; }
    bool m_ab = (vc <= 0.0) && (d1 >= 0.0) && (d3 <= 0.0);
    if (m_ab) { rx = ax + v_ab*abx; ry = ay + v_ab*aby; rz = az + v_ab*abz; }
    bool m_c = (d6 >= 0.0) && (d5 <= d6);
    if (m_c) { rx = cx; ry = cy; rz = cz; }
    bool m_b = (d3 >= 0.0) && (d4 <= d3);
    if (m_b) { rx = bx; ry = by; rz = bz; }
    bool m_a = (d1 <= 0.0) && (d2 <= 0.0);
    if (m_a) { rx = ax; ry = ay; rz = az; }

    double dxx = px - rx, dyy = py - ry, dzz = pz - rz;
    d2out = dxx*dxx + dyy*dyy + dzz*dzz;
    rxo = rx; ryo = ry; rzo = rz;
}

// ---------------------------------------------------------------------------
// Kernel 2: arbitrate the <=8 candidates per point in double precision, write
// outputs: dist[32768] | closest[32768*3] | faces[32768] (as float).
// ---------------------------------------------------------------------------
__global__ void k_fin(const float* __restrict__ tris,
                      const float* __restrict__ points,
                      float* __restrict__ out) {
    int i = blockIdx.x * blockDim.x + threadIdx.x;
    if (i >= NPTS) return;
    int b = i / NQ;

    const float* pp = points + (size_t)i * 3;
    double px = pp[0], py = pp[1], pz = pp[2];

    double bestD = 1e300, brx = 0, bry = 0, brz = 0;
    int bestI = 0x7FFFFFFF;

    #pragma unroll
    for (int s = 0; s < SPLITS; s++) {
        uint2 c = g_cand[(size_t)i * SPLITS + s];
        #pragma unroll
        for (int k = 0; k < 2; k++) {
            int idx = (k == 0) ? (int)c.x : (int)c.y;
            const float* tp = tris + (size_t)(b * NF + idx) * 9;
            double d2, rx, ry, rz;
            ref_eval_d(tp, px, py, pz, d2, rx, ry, rz);
            bool take = (d2 < bestD) || (d2 == bestD && idx < bestI);
            if (take) { bestD = d2; bestI = idx; brx = rx; bry = ry; brz = rz; }
        }
    }

    out[i] = (float)bestD;                               // distances [2,16384]
    out[NPTS + (size_t)i*3 + 0] = (float)brx;            // closest_points [2,16384,3]
    out[NPTS + (size_t)i*3 + 1] = (float)bry;
    out[NPTS + (size_t)i*3 + 2] = (float)brz;
    out[(size_t)NPTS*4 + i] = (float)bestI;              // closest_faces [2,16384]
}

extern "C" void kernel_launch(void* const* d_in, const int* in_sizes, int n_in,
                              void* d_out, int out_size) {
    const float* tris = (const float*)d_in[0];   // [2,4096,3,3]
    const float* pts  = (const float*)d_in[1];   // [2,16384,3]
    float* out = (float*)d_out;

    k_pre<<<(NB*NF + 255) / 256, 256>>>(tris);
    dim3 grid(NQ / BLOCK, SPLITS, NB);
    k_main<<<grid, BLOCK>>>(pts);
    k_fin<<<(NPTS + 255) / 256, 256>>>(tris, pts, out);
}